// round 9
// baseline (speedup 1.0000x reference)
#include <cuda_runtime.h>
#include <math.h>

#define N_NODES 100000
#define N_GRAPHS 1000
#define D 64
#define H 128
#define CAP 64            // max in-degree capacity (actual max ~32 for Poisson(10)+ring)

// Scratch (alloc-free rule: __device__ globals)
__device__ int   g_cursor[N_NODES];          // becomes in-degree after fill
__device__ float g_dinv[N_NODES];
__device__ int   g_esrc[N_NODES * CAP];      // bucketed edge lists (25.6 MB)
__device__ float g_x[N_NODES * D];           // producer output (pre-scaled by dinv[row])
__device__ float g_h[N_NODES * D];           // layer-1 output (pre-scaled)
__device__ float g_pool[N_GRAPHS * D];
__device__ float g_cnt[N_GRAPHS];

// ---------------------------------------------------------------------------
// Bucketed CSR fill: cursor counts in-degree, esrc[d*CAP + pos] = s.
__global__ void fill_kernel(const int* __restrict__ src,
                            const int* __restrict__ dst, int E) {
    int i = blockIdx.x * blockDim.x + threadIdx.x;
    if (i >= E) return;
    int d = dst[i];
    int pos = atomicAdd(&g_cursor[d], 1);
    if (pos < CAP) g_esrc[(size_t)d * CAP + pos] = src[i];
}

__global__ void dinv_kernel() {
    int n = blockIdx.x * blockDim.x + threadIdx.x;
    if (n < N_NODES) g_dinv[n] = rsqrtf((float)(min(g_cursor[n], CAP) + 1));
}

// ---------------------------------------------------------------------------
// Y[N,64] = (X[N,64] @ W[64,64]) * dinv[row]    (runs AFTER dinv_kernel)
__global__ void gemm64_kernel(const float* __restrict__ X,
                              const float* __restrict__ W,
                              float* __restrict__ Y) {
    __shared__ float sW[D * D];
    __shared__ float sx[32 * D];
    int t = threadIdx.x;
    int row0 = blockIdx.x * 32;
    for (int i = t; i < D * D; i += 256) sW[i] = W[i];
    for (int i = t; i < 32 * D; i += 256) sx[i] = X[row0 * D + i];
    __syncthreads();
    int j = t & 63;
    int rg = t >> 6;
    float acc[8];
#pragma unroll
    for (int i = 0; i < 8; i++) acc[i] = 0.f;
#pragma unroll
    for (int k = 0; k < D; k++) {
        float w = sW[k * D + j];
#pragma unroll
        for (int i = 0; i < 8; i++)
            acc[i] += sx[(rg * 8 + i) * D + k] * w;
    }
#pragma unroll
    for (int i = 0; i < 8; i++) {
        int row = row0 + rg * 8 + i;
        Y[row * D + j] = acc[i] * g_dinv[row];
    }
}

// ---------------------------------------------------------------------------
// Gather, half-warp (16 lanes x float4) per node. Input X4 pre-scaled by
// dinv[src]: hot loop is pure load+add.
//   t[n] = dinv[n] * (sum_{s in N(n)} x'[s] + x'[n])
//   MODE 1 (layer 1): out[n] = relu(t[n] + b) * dinv[n]       -> write g_h
//   MODE 0 (layer 2): red.v4  g_pool[batch[n]] += t[n] ; cnt  -> no z buffer
template <int MODE>
__global__ void gather_kernel(const float4* __restrict__ X4,
                              float4* __restrict__ out,
                              const float4* __restrict__ b4,
                              const int* __restrict__ batch) {
    int node = (blockIdx.x * blockDim.x + threadIdx.x) >> 4;
    int lane = threadIdx.x & 31;
    int hl = lane & 15;
    int deg = min(g_cursor[node], CAP);
    int maxdeg = max(deg, __shfl_xor_sync(0xffffffffu, deg, 16));
    const int* rowp = g_esrc + (size_t)node * CAP;
    float4 acc = make_float4(0.f, 0.f, 0.f, 0.f);
    for (int j = 0; j < maxdeg; j += 16) {
        int s = ((j + hl) < deg) ? rowp[j + hl] : 0;
        int cnt = min(16, maxdeg - j);
        for (int i = 0; i < cnt; i++) {
            int si = __shfl_sync(0xffffffffu, s, (lane & 16) + i);
            if ((j + i) < deg) {
                float4 v = X4[(size_t)si * 16 + hl];
                acc.x += v.x; acc.y += v.y; acc.z += v.z; acc.w += v.w;
            }
        }
    }
    float di = g_dinv[node];
    float4 xv = X4[(size_t)node * 16 + hl];
    float4 o;
    o.x = (acc.x + xv.x) * di;
    o.y = (acc.y + xv.y) * di;
    o.z = (acc.z + xv.z) * di;
    o.w = (acc.w + xv.w) * di;
    if (MODE == 1) {
        float4 bb = b4[hl];
        o.x = fmaxf(o.x + bb.x, 0.f) * di;
        o.y = fmaxf(o.y + bb.y, 0.f) * di;
        o.z = fmaxf(o.z + bb.z, 0.f) * di;
        o.w = fmaxf(o.w + bb.w, 0.f) * di;
        out[(size_t)node * 16 + hl] = o;
    } else {
        int g = __ldg(batch + node);
        float* p = g_pool + g * D + hl * 4;
        asm volatile("red.global.add.v4.f32 [%0], {%1, %2, %3, %4};"
                     :: "l"(p), "f"(o.x), "f"(o.y), "f"(o.z), "f"(o.w)
                     : "memory");
        if (hl == 0) atomicAdd(&g_cnt[g], 1.f);
    }
}

// ---------------------------------------------------------------------------
// Head: q = mean(z) @ W2 + b2 ; out = sigmoid(relu(q @ mW1 + mb1) @ mW2 + mb2)
__global__ void mlp_kernel(const float* __restrict__ W2,
                           const float* __restrict__ b2,
                           const float* __restrict__ mW1,
                           const float* __restrict__ mb1,
                           const float* __restrict__ mW2,
                           const float* __restrict__ mb2,
                           float* __restrict__ out) {
    __shared__ float p[D];
    __shared__ float q[D];
    __shared__ float red[H];
    int g = blockIdx.x, t = threadIdx.x;
    if (t < D) {
        float c = fmaxf(g_cnt[g], 1.f);
        p[t] = g_pool[g * D + t] / c;
    }
    __syncthreads();
    if (t < D) {
        float a = b2[t];
#pragma unroll
        for (int k = 0; k < D; k++) a += p[k] * W2[k * D + t];
        q[t] = a;
    }
    __syncthreads();
    float acc = mb1[t];
#pragma unroll
    for (int k = 0; k < D; k++) acc += q[k] * mW1[k * H + t];
    red[t] = fmaxf(acc, 0.f) * mW2[t];
    __syncthreads();
    for (int s = H / 2; s > 0; s >>= 1) {
        if (t < s) red[t] += red[t + s];
        __syncthreads();
    }
    if (t == 0) out[g] = 1.f / (1.f + expf(-(red[0] + mb2[0])));
}

// ---------------------------------------------------------------------------
extern "C" void kernel_launch(void* const* d_in, const int* in_sizes, int n_in,
                              void* d_out, int out_size) {
    const int*   edge_index = (const int*)d_in[0];
    const int*   batch      = (const int*)d_in[1];
    const float* emb        = (const float*)d_in[2];
    const float* W1         = (const float*)d_in[3];
    const float* b1         = (const float*)d_in[4];
    const float* W2         = (const float*)d_in[5];
    const float* b2         = (const float*)d_in[6];
    const float* mW1        = (const float*)d_in[7];
    const float* mb1        = (const float*)d_in[8];
    const float* mW2        = (const float*)d_in[9];
    const float* mb2        = (const float*)d_in[10];
    float* out = (float*)d_out;

    int E = in_sizes[0] / 2;
    const int* src = edge_index;
    const int* dst = edge_index + E;

    void *p_cursor, *p_x, *p_h, *p_pool, *p_cnt;
    cudaGetSymbolAddress(&p_cursor, g_cursor);
    cudaGetSymbolAddress(&p_x,      g_x);
    cudaGetSymbolAddress(&p_h,      g_h);
    cudaGetSymbolAddress(&p_pool,   g_pool);
    cudaGetSymbolAddress(&p_cnt,    g_cnt);
    float* xbuf = (float*)p_x;
    float* hbuf = (float*)p_h;

    const int TPB = 256;

    // CSR build + dinv (single stream, strictly ordered)
    cudaMemsetAsync(p_cursor, 0, N_NODES * sizeof(int));
    cudaMemsetAsync(p_pool, 0, (size_t)N_GRAPHS * D * sizeof(float));
    cudaMemsetAsync(p_cnt,  0, (size_t)N_GRAPHS * sizeof(float));
    fill_kernel<<<(E + TPB - 1) / TPB, TPB>>>(src, dst, E);
    dinv_kernel<<<(N_NODES + TPB - 1) / TPB, TPB>>>();

    // ---- Layer 1: x' = (emb @ W1)*dinv ; y' = relu(Agg(x') + b1)*dinv
    gemm64_kernel<<<N_NODES / 32, 256>>>(emb, W1, xbuf);
    gather_kernel<1><<<N_NODES * 16 / TPB, TPB>>>(
        (const float4*)xbuf, (float4*)hbuf, (const float4*)b1, batch);

    // ---- Layer 2 aggregation fused with pool: reds into g_pool/g_cnt
    gather_kernel<0><<<N_NODES * 16 / TPB, TPB>>>(
        (const float4*)hbuf, (float4*)xbuf, (const float4*)b2, batch);

    // ---- Head (W2/b2 + MLP)
    mlp_kernel<<<N_GRAPHS, H>>>(W2, b2, mW1, mb1, mW2, mb2, out);
}

// round 10
// speedup vs baseline: 1.0732x; 1.0732x over previous
#include <cuda_runtime.h>
#include <math.h>

#define N_NODES 100000
#define N_GRAPHS 1000
#define D 64
#define H 128
#define CAP 64            // max in-degree capacity (actual max ~32 for Poisson(10)+ring)
#define ZROW N_NODES      // zero-row index (stays zero: statics zero-init, never written)

// Scratch (alloc-free rule: __device__ globals). cursor/pool/cnt share one
// struct so a single memset clears all per-run state.
struct ZeroRegion {
    int   cursor[N_NODES];      // becomes in-degree after fill
    float pool[N_GRAPHS * D];
    float cnt[N_GRAPHS];
};
__device__ ZeroRegion g_z;
__device__ int   g_esrc[N_NODES * CAP];        // bucketed edge lists (25.6 MB)
__device__ float g_x[(N_NODES + 1) * D];       // +1 zero row for pad loads
__device__ float g_h[(N_NODES + 1) * D];       // +1 zero row for pad loads

// ---------------------------------------------------------------------------
// Bucketed CSR fill: cursor counts in-degree, esrc[d*CAP + pos] = s.
__global__ void fill_kernel(const int* __restrict__ src,
                            const int* __restrict__ dst, int E) {
    int i = blockIdx.x * blockDim.x + threadIdx.x;
    if (i >= E) return;
    int d = dst[i];
    int pos = atomicAdd(&g_z.cursor[d], 1);
    if (pos < CAP) g_esrc[(size_t)d * CAP + pos] = src[i];
}

// ---------------------------------------------------------------------------
// Y[N,64] = (X[N,64] @ W[64,64]) * rsqrt(deg[row]+1)
__global__ void gemm64_kernel(const float* __restrict__ X,
                              const float* __restrict__ W,
                              float* __restrict__ Y) {
    __shared__ float sW[D * D];
    __shared__ float sx[32 * D];
    int t = threadIdx.x;
    int row0 = blockIdx.x * 32;
    for (int i = t; i < D * D; i += 256) sW[i] = W[i];
    for (int i = t; i < 32 * D; i += 256) sx[i] = X[row0 * D + i];
    __syncthreads();
    int j = t & 63;
    int rg = t >> 6;
    float acc[8];
#pragma unroll
    for (int i = 0; i < 8; i++) acc[i] = 0.f;
#pragma unroll
    for (int k = 0; k < D; k++) {
        float w = sW[k * D + j];
#pragma unroll
        for (int i = 0; i < 8; i++)
            acc[i] += sx[(rg * 8 + i) * D + k] * w;
    }
#pragma unroll
    for (int i = 0; i < 8; i++) {
        int row = row0 + rg * 8 + i;
        float di = rsqrtf((float)(min(g_z.cursor[row], CAP) + 1));
        Y[row * D + j] = acc[i] * di;
    }
}

// ---------------------------------------------------------------------------
// Gather, half-warp (16 lanes x float4) per node. Input X4 pre-scaled by
// dinv[src]. Inner loop is fixed-trip (16) and fully unrolled: out-of-degree
// lanes read the zero row, so no predication in the hot path.
//   t[n] = dinv[n] * (sum_{s in N(n)} x'[s] + x'[n])
//   MODE 1 (layer 1): out[n] = relu(t[n] + b) * dinv[n]       -> write g_h
//   MODE 0 (layer 2): red.v4  g_z.pool[batch[n]] += t[n]; cnt -> no z buffer
//                     (the warp's two nodes usually share a graph id: combine
//                      via shfl and issue ONE red for both)
template <int MODE>
__global__ void gather_kernel(const float4* __restrict__ X4,
                              float4* __restrict__ out,
                              const float4* __restrict__ b4,
                              const int* __restrict__ batch) {
    int node = (blockIdx.x * blockDim.x + threadIdx.x) >> 4;
    int lane = threadIdx.x & 31;
    int hl = lane & 15;
    int deg = min(g_z.cursor[node], CAP);
    int maxdeg = max(deg, __shfl_xor_sync(0xffffffffu, deg, 16));
    const int* rowp = g_esrc + (size_t)node * CAP;
    float4 acc = make_float4(0.f, 0.f, 0.f, 0.f);
    for (int j = 0; j < maxdeg; j += 16) {
        int s = ((j + hl) < deg) ? rowp[j + hl] : ZROW;
#pragma unroll
        for (int i = 0; i < 16; i++) {
            int si = __shfl_sync(0xffffffffu, s, (lane & 16) + i);
            float4 v = X4[(size_t)si * 16 + hl];
            acc.x += v.x; acc.y += v.y; acc.z += v.z; acc.w += v.w;
        }
    }
    float di = rsqrtf((float)(deg + 1));
    float4 xv = X4[(size_t)node * 16 + hl];
    float4 o;
    o.x = (acc.x + xv.x) * di;
    o.y = (acc.y + xv.y) * di;
    o.z = (acc.z + xv.z) * di;
    o.w = (acc.w + xv.w) * di;
    if (MODE == 1) {
        float4 bb = b4[hl];
        o.x = fmaxf(o.x + bb.x, 0.f) * di;
        o.y = fmaxf(o.y + bb.y, 0.f) * di;
        o.z = fmaxf(o.z + bb.z, 0.f) * di;
        o.w = fmaxf(o.w + bb.w, 0.f) * di;
        out[(size_t)node * 16 + hl] = o;
    } else {
        int g = __ldg(batch + node);
        int go = __shfl_xor_sync(0xffffffffu, g, 16);
        float rx = __shfl_xor_sync(0xffffffffu, o.x, 16);
        float ry = __shfl_xor_sync(0xffffffffu, o.y, 16);
        float rz = __shfl_xor_sync(0xffffffffu, o.z, 16);
        float rw = __shfl_xor_sync(0xffffffffu, o.w, 16);
        if (g == go) {
            if (lane < 16) {
                o.x += rx; o.y += ry; o.z += rz; o.w += rw;
                float* p = g_z.pool + g * D + hl * 4;
                asm volatile("red.global.add.v4.f32 [%0], {%1, %2, %3, %4};"
                             :: "l"(p), "f"(o.x), "f"(o.y), "f"(o.z), "f"(o.w)
                             : "memory");
                if (hl == 0) atomicAdd(&g_z.cnt[g], 2.f);
            }
        } else {
            float* p = g_z.pool + g * D + hl * 4;
            asm volatile("red.global.add.v4.f32 [%0], {%1, %2, %3, %4};"
                         :: "l"(p), "f"(o.x), "f"(o.y), "f"(o.z), "f"(o.w)
                         : "memory");
            if (hl == 0) atomicAdd(&g_z.cnt[g], 1.f);
        }
    }
}

// ---------------------------------------------------------------------------
// Head: q = mean(z) @ W2 + b2 ; out = sigmoid(relu(q @ mW1 + mb1) @ mW2 + mb2)
__global__ void mlp_kernel(const float* __restrict__ W2,
                           const float* __restrict__ b2,
                           const float* __restrict__ mW1,
                           const float* __restrict__ mb1,
                           const float* __restrict__ mW2,
                           const float* __restrict__ mb2,
                           float* __restrict__ out) {
    __shared__ float p[D];
    __shared__ float q[D];
    __shared__ float red[H];
    int g = blockIdx.x, t = threadIdx.x;
    if (t < D) {
        float c = fmaxf(g_z.cnt[g], 1.f);
        p[t] = g_z.pool[g * D + t] / c;
    }
    __syncthreads();
    if (t < D) {
        float a = b2[t];
#pragma unroll
        for (int k = 0; k < D; k++) a += p[k] * W2[k * D + t];
        q[t] = a;
    }
    __syncthreads();
    float acc = mb1[t];
#pragma unroll
    for (int k = 0; k < D; k++) acc += q[k] * mW1[k * H + t];
    red[t] = fmaxf(acc, 0.f) * mW2[t];
    __syncthreads();
    for (int s = H / 2; s > 0; s >>= 1) {
        if (t < s) red[t] += red[t + s];
        __syncthreads();
    }
    if (t == 0) out[g] = 1.f / (1.f + expf(-(red[0] + mb2[0])));
}

// ---------------------------------------------------------------------------
extern "C" void kernel_launch(void* const* d_in, const int* in_sizes, int n_in,
                              void* d_out, int out_size) {
    const int*   edge_index = (const int*)d_in[0];
    const int*   batch      = (const int*)d_in[1];
    const float* emb        = (const float*)d_in[2];
    const float* W1         = (const float*)d_in[3];
    const float* b1         = (const float*)d_in[4];
    const float* W2         = (const float*)d_in[5];
    const float* b2         = (const float*)d_in[6];
    const float* mW1        = (const float*)d_in[7];
    const float* mb1        = (const float*)d_in[8];
    const float* mW2        = (const float*)d_in[9];
    const float* mb2        = (const float*)d_in[10];
    float* out = (float*)d_out;

    int E = in_sizes[0] / 2;
    const int* src = edge_index;
    const int* dst = edge_index + E;

    void *p_z, *p_x, *p_h;
    cudaGetSymbolAddress(&p_z, g_z);
    cudaGetSymbolAddress(&p_x, g_x);
    cudaGetSymbolAddress(&p_h, g_h);
    float* xbuf = (float*)p_x;
    float* hbuf = (float*)p_h;

    const int TPB = 256;

    // One memset clears cursor + pool + cnt; then CSR fill.
    cudaMemsetAsync(p_z, 0, sizeof(ZeroRegion));
    fill_kernel<<<(E + TPB - 1) / TPB, TPB>>>(src, dst, E);

    // ---- Layer 1: x' = (emb @ W1)*dinv ; y' = relu(Agg(x') + b1)*dinv
    gemm64_kernel<<<N_NODES / 32, 256>>>(emb, W1, xbuf);
    gather_kernel<1><<<N_NODES * 16 / TPB, TPB>>>(
        (const float4*)xbuf, (float4*)hbuf, (const float4*)b1, batch);

    // ---- Layer 2 aggregation fused with pool: reds into g_z.pool/g_z.cnt
    gather_kernel<0><<<N_NODES * 16 / TPB, TPB>>>(
        (const float4*)hbuf, (float4*)xbuf, (const float4*)b2, batch);

    // ---- Head (W2/b2 + MLP)
    mlp_kernel<<<N_GRAPHS, H>>>(W2, b2, mW1, mb1, mW2, mb2, out);
}